// round 1
// baseline (speedup 1.0000x reference)
#include <cuda_runtime.h>
#include <math.h>

#define NEURONS 54
#define NPAD    64
#define DT      4
#define STEPS   30
#define BATCHES 128
#define RG      75    // pooled row groups
#define PCOLS   75    // pooled cols per row group
#define BATCH_PER_BLK 8

// scratch (no allocations allowed)
__device__ float g_partial[BATCHES * RG * NPAD];  // [b][r][n] fc partial sums
__device__ float g_expxf[BATCHES * NPAD];         // exp(xf), 0 for padded neurons

// ---------------------------------------------------------------------------
// Kernel 1: stream x once; 8x8 avg-pool one row-group; multiply by the 54x75
// fc_w chunk; write deterministic partials. grid = (75 rowgroups, 16 batch
// tiles), 512 threads.
// ---------------------------------------------------------------------------
__global__ void __launch_bounds__(512) pool_fc_kernel(
    const float* __restrict__ x, const float* __restrict__ fc_w)
{
    __shared__ float colsum[600];
    __shared__ float pooled[80];
    __shared__ float w_s[NEURONS * 76];   // pitch 76 to break conflicts

    const int r   = blockIdx.x;   // row group 0..74
    const int bz  = blockIdx.y;   // batch tile 0..15
    const int tid = threadIdx.x;
    const int lane = tid & 31, wid = tid >> 5;

    // stage fc_w chunk for this row group
    for (int idx = tid; idx < NEURONS * PCOLS; idx += 512) {
        int n = idx / PCOLS, p = idx - n * PCOLS;
        w_s[n * 76 + p] = fc_w[n * 5625 + r * PCOLS + p];
    }
    __syncthreads();

    for (int bb = 0; bb < BATCH_PER_BLK; bb++) {
        const int b = bz * BATCH_PER_BLK + bb;
        const float* xrow = x + ((long)b * 600 + (long)r * 8) * 600;

        // phase A: per-column sum over 8 rows (coalesced)
        for (int c = tid; c < 600; c += 512) {
            float s = 0.f;
#pragma unroll
            for (int rr = 0; rr < 8; rr++) s += xrow[rr * 600 + c];
            colsum[c] = s;
        }
        __syncthreads();

        // phase B: 8-col horizontal sum -> pooled value (mean of 64)
        if (tid < PCOLS) {
            float s = 0.f;
#pragma unroll
            for (int cc = 0; cc < 8; cc++) s += colsum[tid * 8 + cc];
            pooled[tid] = s * (1.f / 64.f);
        }
        __syncthreads();

        // phase C: warp-per-neuron 75-length dot with staged weights
        for (int n = wid; n < NEURONS; n += 16) {
            float v = 0.f;
#pragma unroll
            for (int pp = 0; pp < 3; pp++) {
                int p = lane + pp * 32;
                if (p < PCOLS) v += pooled[p] * w_s[n * 76 + p];
            }
#pragma unroll
            for (int d = 16; d; d >>= 1) v += __shfl_xor_sync(0xffffffffu, v, d);
            if (lane == 0) g_partial[((long)b * RG + r) * NPAD + n] = v;
        }
        __syncthreads();  // before colsum is rewritten next iteration
    }
}

// ---------------------------------------------------------------------------
// Kernel 2: reduce 75 partials per (b,n), add bias, exponentiate.
// grid = 128, block = 64.
// ---------------------------------------------------------------------------
__global__ void reduce_exp_kernel(const float* __restrict__ fc_b)
{
    const int b = blockIdx.x, n = threadIdx.x;
    float v = 0.f;
    if (n < NEURONS) {
        float acc = fc_b[n];
        for (int r = 0; r < RG; r++)
            acc += g_partial[((long)b * RG + r) * NPAD + n];
        v = expf(acc);
    }
    g_expxf[b * NPAD + n] = v;
}

// ---------------------------------------------------------------------------
// Kernel 3: 30-step GLM scan, single block (global mean each step).
// Thread t owns batch b = t/8, neurons g*8..g*8+7 (g = t%8); histories are
// spike bits -> one packed-nibble register per thread.
// rate = exp(xf) * exp(S_b) * LUT_er[n][nib],  LUT_er = exp(h(nib) - hs(nib))
// ---------------------------------------------------------------------------
__global__ void __launch_bounds__(1024) glm_kernel(
    const float* __restrict__ lw, const float* __restrict__ hw,
    float* __restrict__ out)
{
    __shared__ float2 lut[NPAD * 17];  // {hs, exp(h - hs)}, pitch 17
    __shared__ float red[32];
    __shared__ float thr_s;

    const int tid = threadIdx.x;
    const int lane = tid & 31, wid = tid >> 5;

    // build LUT: exactly 64*16 = 1024 entries, one per thread
    {
        int n = tid >> 4, nib = tid & 15;
        float hs = 0.f, h = 0.f;
        if (n < NEURONS) {
#pragma unroll
            for (int t = 0; t < DT; t++)
                if (nib & (1 << t)) { hs += lw[n * DT + t]; h += hw[t]; }
        }
        lut[n * 17 + nib] = make_float2(hs, expf(h - hs));
    }
    __syncthreads();

    const int b = tid >> 3, g = tid & 7;
    const int nbase = g * 8;

    float exf[8];
#pragma unroll
    for (int i = 0; i < 8; i++) exf[i] = g_expxf[b * NPAD + nbase + i];

    unsigned nibs = 0;  // 8 x 4-bit histories
    float cnt[8];
#pragma unroll
    for (int i = 0; i < 8; i++) cnt[i] = 0.f;

    for (int step = 0; step < STEPS; step++) {
        float er[8], sl = 0.f;
#pragma unroll
        for (int i = 0; i < 8; i++) {
            unsigned nib = (nibs >> (4 * i)) & 15u;
            float2 e = lut[(nbase + i) * 17 + nib];
            er[i] = e.y;
            sl += e.x;
        }
        // per-batch sum over 54 neurons: 8 consecutive lanes share a batch
        float S = sl;
        S += __shfl_xor_sync(0xffffffffu, S, 1);
        S += __shfl_xor_sync(0xffffffffu, S, 2);
        S += __shfl_xor_sync(0xffffffffu, S, 4);
        float eS = expf(S);

        float rate[8], rs = 0.f;
#pragma unroll
        for (int i = 0; i < 8; i++) { rate[i] = exf[i] * eS * er[i]; rs += rate[i]; }

        // block-wide sum of rates -> threshold = mean
        float v = rs;
#pragma unroll
        for (int d = 16; d; d >>= 1) v += __shfl_xor_sync(0xffffffffu, v, d);
        if (lane == 0) red[wid] = v;
        __syncthreads();
        if (tid < 32) {
            float t = red[tid];
#pragma unroll
            for (int d = 16; d; d >>= 1) t += __shfl_xor_sync(0xffffffffu, t, d);
            if (tid == 0) thr_s = t * (1.f / (BATCHES * NEURONS));
        }
        __syncthreads();
        const float thr = thr_s;

        unsigned nn = 0;
#pragma unroll
        for (int i = 0; i < 8; i++) {
            unsigned nib = (nibs >> (4 * i)) & 15u;
            unsigned sp = (rate[i] > thr) ? 1u : 0u;
            cnt[i] += (float)sp;
            nn |= (((nib >> 1) | (sp << 3)) & 15u) << (4 * i);
        }
        nibs = nn;
    }

    // softplus(count), stable form (count >= 0)
#pragma unroll
    for (int i = 0; i < 8; i++) {
        int n = nbase + i;
        if (n < NEURONS) {
            float c = cnt[i];
            out[b * NEURONS + n] = c + log1pf(expf(-c));
        }
    }
}

extern "C" void kernel_launch(void* const* d_in, const int* in_sizes, int n_in,
                              void* d_out, int out_size)
{
    const float* x   = (const float*)d_in[0];  // [128,1,600,600]
    const float* lw  = (const float*)d_in[1];  // [54,4]
    const float* hw  = (const float*)d_in[2];  // [4]
    const float* fcw = (const float*)d_in[3];  // [54,5625]
    const float* fcb = (const float*)d_in[4];  // [54]
    float* out = (float*)d_out;                // [128,54]

    pool_fc_kernel<<<dim3(75, 16), 512>>>(x, fcw);
    reduce_exp_kernel<<<128, 64>>>(fcb);
    glm_kernel<<<1, 1024>>>(lw, hw, out);
}

// round 2
// speedup vs baseline: 1.2891x; 1.2891x over previous
#include <cuda_runtime.h>
#include <math.h>

#define NEURONS 54
#define NPAD    64
#define DT      4
#define STEPS   30
#define BATCHES 128
#define KDIM    5625      // 75*75
#define KPAD    5632      // 44*128
#define KC      128       // K chunk for FC
#define NKC     44        // 5632/128

// scratch (zero-initialized device globals; pads are never written -> stay 0)
__device__ float g_pooled[BATCHES * KPAD];          // [b][k], k>=5625 zero
__device__ float g_fcpart[NKC * BATCHES * NPAD];    // [kc][b][n]
__device__ float g_expxf[BATCHES * NPAD];           // exp(xf), 0 for pad neurons

// ---------------------------------------------------------------------------
// Kernel 1: pure streaming 8x8 avg-pool. One thread per pooled output,
// 16 independent LDG.128, no barriers, no smem.
// ---------------------------------------------------------------------------
__global__ void __launch_bounds__(256) pool_kernel(const float* __restrict__ x)
{
    int idx = blockIdx.x * 256 + threadIdx.x;
    if (idx >= BATCHES * KDIM) return;
    int b  = idx / KDIM;
    int r  = idx - b * KDIM;     // 0..5624
    int rg = r / 75;
    int p  = r - rg * 75;

    const float4* xp = (const float4*)x + ((b * 600 + rg * 8) * 150 + p * 2);
    float s = 0.f;
#pragma unroll
    for (int rr = 0; rr < 8; rr++) {
        float4 a = xp[rr * 150];
        float4 c = xp[rr * 150 + 1];
        s += (a.x + a.y) + (a.z + a.w) + (c.x + c.y) + (c.z + c.w);
    }
    g_pooled[b * KPAD + r] = s * (1.f / 64.f);
}

// ---------------------------------------------------------------------------
// Kernel 2: split-K FC partials. grid = (44 K-chunks, 8 batch-tiles of 16).
// W chunk staged in smem (27.6KB); each warp holds 2 batches' P-frags in regs.
// ---------------------------------------------------------------------------
__global__ void __launch_bounds__(256) fc_kernel(const float* __restrict__ fc_w)
{
    __shared__ __align__(16) float Ws[NEURONS * KC];

    const int kc  = blockIdx.x;          // 0..43
    const int bt  = blockIdx.y;          // 0..7
    const int tid = threadIdx.x;
    const int k0  = kc * KC;

    for (int i = tid; i < NEURONS * KC; i += 256) {
        int n = i / KC, k = i - n * KC;
        int kg = k0 + k;
        Ws[i] = (kg < KDIM) ? fc_w[n * KDIM + kg] : 0.f;
    }
    __syncthreads();

    const int w = tid >> 5, lane = tid & 31;
    const int b0 = bt * 16 + w * 2;

    float4 p0 = ((const float4*)(g_pooled + (size_t)b0 * KPAD + k0))[lane];
    float4 p1 = ((const float4*)(g_pooled + (size_t)(b0 + 1) * KPAD + k0))[lane];
    const float4* W4 = (const float4*)Ws;

    for (int n = 0; n < NEURONS; n++) {
        float4 wv = W4[n * 32 + lane];
        float a0 = p0.x * wv.x + p0.y * wv.y + p0.z * wv.z + p0.w * wv.w;
        float a1 = p1.x * wv.x + p1.y * wv.y + p1.z * wv.z + p1.w * wv.w;
#pragma unroll
        for (int d = 16; d; d >>= 1) {
            a0 += __shfl_xor_sync(0xffffffffu, a0, d);
            a1 += __shfl_xor_sync(0xffffffffu, a1, d);
        }
        if (lane == 0) {
            g_fcpart[(kc * BATCHES + b0) * NPAD + n]     = a0;
            g_fcpart[(kc * BATCHES + b0 + 1) * NPAD + n] = a1;
        }
    }
}

// ---------------------------------------------------------------------------
// Kernel 3: reduce 44 K-partials, add bias, exponentiate. grid=128, block=64.
// ---------------------------------------------------------------------------
__global__ void reduce_exp_kernel(const float* __restrict__ fc_b)
{
    const int b = blockIdx.x, n = threadIdx.x;
    float a = 0.f;
#pragma unroll 4
    for (int kc = 0; kc < NKC; kc++)
        a += g_fcpart[(kc * BATCHES + b) * NPAD + n];
    float v = 0.f;
    if (n < NEURONS) v = expf(a + fc_b[n]);
    g_expxf[b * NPAD + n] = v;
}

// ---------------------------------------------------------------------------
// Kernel 4: 30-step GLM scan, single block of 1024 (global mean each step).
// Thread t: batch b = t/8, neurons n = (t%8) + 8i (stride-8 -> conflict-free
// LUT banks). History = spike bits -> packed nibbles.
// rate = exp(xf) * exp(S_b) * LUT[n][nib].y, LUT = {hs, exp(h - hs)}.
// One barrier per step via double-buffered reduction slots.
// ---------------------------------------------------------------------------
__global__ void __launch_bounds__(1024) glm_kernel(
    const float* __restrict__ lw, const float* __restrict__ hw,
    float* __restrict__ out)
{
    __shared__ float2 lut[NPAD * 18];   // pitch 18 float2: spread banks
    __shared__ float red[2][32];

    const int tid = threadIdx.x;
    const int lane = tid & 31, wid = tid >> 5;

    // build LUT: 64*16 entries, one per thread
    {
        int n = tid >> 4, nib = tid & 15;
        float hs = 0.f, h = 0.f;
        if (n < NEURONS) {
#pragma unroll
            for (int t = 0; t < DT; t++)
                if (nib & (1 << t)) { hs += lw[n * DT + t]; h += hw[t]; }
        }
        lut[n * 18 + nib] = make_float2(hs, expf(h - hs));
    }

    const int b = tid >> 3, g = tid & 7;

    float exf[8];
#pragma unroll
    for (int i = 0; i < 8; i++) exf[i] = g_expxf[b * NPAD + g + 8 * i];

    __syncthreads();

    unsigned nibs = 0;
    float cnt[8];
#pragma unroll
    for (int i = 0; i < 8; i++) cnt[i] = 0.f;

    for (int step = 0; step < STEPS; step++) {
        float er[8], sl = 0.f;
#pragma unroll
        for (int i = 0; i < 8; i++) {
            unsigned nib = (nibs >> (4 * i)) & 15u;
            float2 e = lut[(g + 8 * i) * 18 + nib];
            er[i] = e.y;
            sl += e.x;
        }
        // per-batch S: 8 consecutive lanes share a batch
        float S = sl;
        S += __shfl_xor_sync(0xffffffffu, S, 1);
        S += __shfl_xor_sync(0xffffffffu, S, 2);
        S += __shfl_xor_sync(0xffffffffu, S, 4);
        float eS = expf(S);

        float rate[8], rs = 0.f;
#pragma unroll
        for (int i = 0; i < 8; i++) { rate[i] = exf[i] * eS * er[i]; rs += rate[i]; }

        // block sum -> mean threshold (1 barrier, double-buffered slots,
        // redundant per-warp final reduce)
        float v = rs;
#pragma unroll
        for (int d = 16; d; d >>= 1) v += __shfl_xor_sync(0xffffffffu, v, d);
        if (lane == 0) red[step & 1][wid] = v;
        __syncthreads();
        float t = red[step & 1][lane];
#pragma unroll
        for (int d = 16; d; d >>= 1) t += __shfl_xor_sync(0xffffffffu, t, d);
        const float thr = t * (1.f / (BATCHES * NEURONS));

        unsigned nn = 0;
#pragma unroll
        for (int i = 0; i < 8; i++) {
            unsigned nib = (nibs >> (4 * i)) & 15u;
            unsigned sp = (rate[i] > thr) ? 1u : 0u;
            cnt[i] += (float)sp;
            nn |= (((nib >> 1) | (sp << 3)) & 15u) << (4 * i);
        }
        nibs = nn;
    }

    // softplus(count), stable (count >= 0)
#pragma unroll
    for (int i = 0; i < 8; i++) {
        int n = g + 8 * i;
        if (n < NEURONS) {
            float c = cnt[i];
            out[b * NEURONS + n] = c + log1pf(expf(-c));
        }
    }
}

extern "C" void kernel_launch(void* const* d_in, const int* in_sizes, int n_in,
                              void* d_out, int out_size)
{
    const float* x   = (const float*)d_in[0];  // [128,1,600,600]
    const float* lw  = (const float*)d_in[1];  // [54,4]
    const float* hw  = (const float*)d_in[2];  // [4]
    const float* fcw = (const float*)d_in[3];  // [54,5625]
    const float* fcb = (const float*)d_in[4];  // [54]
    float* out = (float*)d_out;                // [128,54]

    pool_kernel<<<(BATCHES * KDIM + 255) / 256, 256>>>(x);
    fc_kernel<<<dim3(NKC, 8), 256>>>(fcw);
    reduce_exp_kernel<<<BATCHES, NPAD>>>(fcb);
    glm_kernel<<<1, 1024>>>(lw, hw, out);
}

// round 3
// speedup vs baseline: 1.4361x; 1.1140x over previous
#include <cuda_runtime.h>
#include <math.h>
#include <stdint.h>

#define NEURONS 54
#define NPAD    64
#define DT      4
#define STEPS   30
#define BATCHES 128
#define KDIM    5625      // 75*75
#define KPAD    5632      // 44*128
#define KC      128       // K chunk for FC
#define NKC     44        // 5632/128
#define CL      8         // cluster size for glm
#define CTHREADS 128
#define WARPS_TOT 32      // CL * 4 warps

// scratch (zero-initialized device globals; pads never written -> stay 0)
__device__ float g_pooled[BATCHES * KPAD];          // [b][k]
__device__ float g_fcpart[NKC * BATCHES * NPAD];    // [kc][b][n]
__device__ float g_expxf[BATCHES * NPAD];           // exp(xf)

__device__ __forceinline__ uint32_t smem_u32(const void* p) {
    uint32_t a;
    asm("{ .reg .u64 t; cvta.to.shared.u64 t, %1; cvt.u32.u64 %0, t; }"
        : "=r"(a) : "l"(p));
    return a;
}

// ---------------------------------------------------------------------------
// Kernel 1: pure streaming 8x8 avg-pool. One thread per pooled output,
// 16 independent LDG.128, no barriers, no smem.
// ---------------------------------------------------------------------------
__global__ void __launch_bounds__(256) pool_kernel(const float* __restrict__ x)
{
    int idx = blockIdx.x * 256 + threadIdx.x;
    if (idx >= BATCHES * KDIM) return;
    int b  = idx / KDIM;
    int r  = idx - b * KDIM;     // 0..5624
    int rg = r / 75;
    int p  = r - rg * 75;

    const float4* xp = (const float4*)x + ((b * 600 + rg * 8) * 150 + p * 2);
    float s = 0.f;
#pragma unroll
    for (int rr = 0; rr < 8; rr++) {
        float4 a = xp[rr * 150];
        float4 c = xp[rr * 150 + 1];
        s += (a.x + a.y) + (a.z + a.w) + (c.x + c.y) + (c.z + c.w);
    }
    g_pooled[b * KPAD + r] = s * (1.f / 64.f);
}

// ---------------------------------------------------------------------------
// Kernel 2: split-K FC partials. grid = (44 K-chunks, 8 batch-tiles of 16).
// ---------------------------------------------------------------------------
__global__ void __launch_bounds__(256) fc_kernel(const float* __restrict__ fc_w)
{
    __shared__ __align__(16) float Ws[NEURONS * KC];

    const int kc  = blockIdx.x;          // 0..43
    const int bt  = blockIdx.y;          // 0..7
    const int tid = threadIdx.x;
    const int k0  = kc * KC;

    for (int i = tid; i < NEURONS * KC; i += 256) {
        int n = i / KC, k = i - n * KC;
        int kg = k0 + k;
        Ws[i] = (kg < KDIM) ? fc_w[n * KDIM + kg] : 0.f;
    }
    __syncthreads();

    const int w = tid >> 5, lane = tid & 31;
    const int b0 = bt * 16 + w * 2;

    float4 p0 = ((const float4*)(g_pooled + (size_t)b0 * KPAD + k0))[lane];
    float4 p1 = ((const float4*)(g_pooled + (size_t)(b0 + 1) * KPAD + k0))[lane];
    const float4* W4 = (const float4*)Ws;

    for (int n = 0; n < NEURONS; n++) {
        float4 wv = W4[n * 32 + lane];
        float a0 = p0.x * wv.x + p0.y * wv.y + p0.z * wv.z + p0.w * wv.w;
        float a1 = p1.x * wv.x + p1.y * wv.y + p1.z * wv.z + p1.w * wv.w;
#pragma unroll
        for (int d = 16; d; d >>= 1) {
            a0 += __shfl_xor_sync(0xffffffffu, a0, d);
            a1 += __shfl_xor_sync(0xffffffffu, a1, d);
        }
        if (lane == 0) {
            g_fcpart[(kc * BATCHES + b0) * NPAD + n]     = a0;
            g_fcpart[(kc * BATCHES + b0 + 1) * NPAD + n] = a1;
        }
    }
}

// ---------------------------------------------------------------------------
// Kernel 3: reduce 44 K-partials, add bias, exponentiate. grid=128, block=64.
// ---------------------------------------------------------------------------
__global__ void reduce_exp_kernel(const float* __restrict__ fc_b)
{
    const int b = blockIdx.x, n = threadIdx.x;
    float a = 0.f;
#pragma unroll 4
    for (int kc = 0; kc < NKC; kc++)
        a += g_fcpart[(kc * BATCHES + b) * NPAD + n];
    float v = 0.f;
    if (n < NEURONS) v = expf(a + fc_b[n]);
    g_expxf[b * NPAD + n] = v;
}

// ---------------------------------------------------------------------------
// Kernel 4: 30-step GLM scan over an 8-CTA CLUSTER (8 SMs).
// CTA rank owns batches rank*16..rank*16+15. Thread: b = rank*16 + tid/8,
// neurons n = (tid&7) + 8i (stride-8 -> conflict-free LUT banks).
// Per step: warp partial of rates -> lane0 multicasts it to gat[parity][gwid]
// in ALL 8 CTAs via mapa + st.shared::cluster -> ONE barrier.cluster ->
// every thread sums 32 local partials -> global mean threshold.
// Double-buffered gat (reuse distance 2 steps spans a cluster barrier).
// ---------------------------------------------------------------------------
__global__ void __launch_bounds__(CTHREADS, 1) __cluster_dims__(CL, 1, 1)
glm_kernel(const float* __restrict__ lw, const float* __restrict__ hw,
           float* __restrict__ out)
{
    __shared__ float2 lut[NPAD * 18];                 // {hs, exp(h-hs)}
    __shared__ __align__(16) float gat[2][WARPS_TOT]; // [parity][global warp]

    const int tid = threadIdx.x;
    const int lane = tid & 31, wid = tid >> 5;
    uint32_t rank;
    asm("mov.u32 %0, %%cluster_ctarank;" : "=r"(rank));
    const int gwid = (int)rank * 4 + wid;

    // build LUT: 1024 entries / 128 threads
    for (int e = tid; e < NPAD * 16; e += CTHREADS) {
        int n = e >> 4, nib = e & 15;
        float hs = 0.f, h = 0.f;
        if (n < NEURONS) {
#pragma unroll
            for (int t = 0; t < DT; t++)
                if (nib & (1 << t)) { hs += lw[n * DT + t]; h += hw[t]; }
        }
        lut[n * 18 + nib] = make_float2(hs, expf(h - hs));
    }

    const int b = (int)rank * 16 + (tid >> 3);
    const int g = tid & 7;

    float exf[8];
#pragma unroll
    for (int i = 0; i < 8; i++) exf[i] = g_expxf[b * NPAD + g + 8 * i];

    // remote addresses of my slot (buffer 0) in every CTA
    uint32_t rem[CL];
    {
        uint32_t base = smem_u32(&gat[0][0]) + (uint32_t)gwid * 4u;
#pragma unroll
        for (int r = 0; r < CL; r++)
            asm("mapa.shared::cluster.u32 %0, %1, %2;"
                : "=r"(rem[r]) : "r"(base), "r"(r));
    }

    __syncthreads();
    asm volatile("barrier.cluster.arrive.aligned;" ::: "memory");
    asm volatile("barrier.cluster.wait.aligned;"   ::: "memory");

    unsigned nibs = 0;
    float cnt[8];
#pragma unroll
    for (int i = 0; i < 8; i++) cnt[i] = 0.f;

    for (int step = 0; step < STEPS; step++) {
        const uint32_t par_off = (step & 1) ? (WARPS_TOT * 4u) : 0u;

        float er[8], sl = 0.f;
#pragma unroll
        for (int i = 0; i < 8; i++) {
            unsigned nib = (nibs >> (4 * i)) & 15u;
            float2 e = lut[(g + 8 * i) * 18 + nib];
            er[i] = e.y;
            sl += e.x;
        }
        // per-batch S: 8 consecutive lanes share a batch
        float S = sl;
        S += __shfl_xor_sync(0xffffffffu, S, 1);
        S += __shfl_xor_sync(0xffffffffu, S, 2);
        S += __shfl_xor_sync(0xffffffffu, S, 4);
        float eS = expf(S);

        float rate[8], rs = 0.f;
#pragma unroll
        for (int i = 0; i < 8; i++) { rate[i] = exf[i] * eS * er[i]; rs += rate[i]; }

        // warp partial
#pragma unroll
        for (int d = 16; d; d >>= 1) rs += __shfl_xor_sync(0xffffffffu, rs, d);

        // lane0 multicasts warp partial into all CTAs' gat[par][gwid]
        if (lane == 0) {
#pragma unroll
            for (int r = 0; r < CL; r++)
                asm volatile("st.shared::cluster.f32 [%0], %1;"
                             :: "r"(rem[r] + par_off), "f"(rs) : "memory");
        }

        // one cluster barrier: arrive(release) orders the remote stores,
        // wait(acquire) makes them visible in local smem.
        asm volatile("barrier.cluster.arrive.aligned;" ::: "memory");
        asm volatile("barrier.cluster.wait.aligned;"   ::: "memory");

        // redundant local sum of 32 warp partials
        const float4* gp = (const float4*)&gat[step & 1][0];
        float t0 = 0.f, t1 = 0.f;
#pragma unroll
        for (int q = 0; q < 8; q += 2) {
            float4 v0 = gp[q], v1 = gp[q + 1];
            t0 += (v0.x + v0.y) + (v0.z + v0.w);
            t1 += (v1.x + v1.y) + (v1.z + v1.w);
        }
        const float thr = (t0 + t1) * (1.f / (BATCHES * NEURONS));

        unsigned nn = 0;
#pragma unroll
        for (int i = 0; i < 8; i++) {
            unsigned nib = (nibs >> (4 * i)) & 15u;
            unsigned sp = (rate[i] > thr) ? 1u : 0u;
            cnt[i] += (float)sp;
            nn |= (((nib >> 1) | (sp << 3)) & 15u) << (4 * i);
        }
        nibs = nn;
    }

    // softplus(count), stable (count >= 0)
#pragma unroll
    for (int i = 0; i < 8; i++) {
        int n = g + 8 * i;
        if (n < NEURONS) {
            float c = cnt[i];
            out[b * NEURONS + n] = c + log1pf(expf(-c));
        }
    }
}

extern "C" void kernel_launch(void* const* d_in, const int* in_sizes, int n_in,
                              void* d_out, int out_size)
{
    const float* x   = (const float*)d_in[0];  // [128,1,600,600]
    const float* lw  = (const float*)d_in[1];  // [54,4]
    const float* hw  = (const float*)d_in[2];  // [4]
    const float* fcw = (const float*)d_in[3];  // [54,5625]
    const float* fcb = (const float*)d_in[4];  // [54]
    float* out = (float*)d_out;                // [128,54]

    pool_kernel<<<(BATCHES * KDIM + 255) / 256, 256>>>(x);
    fc_kernel<<<dim3(NKC, 8), 256>>>(fcw);
    reduce_exp_kernel<<<BATCHES, NPAD>>>(fcb);
    glm_kernel<<<CL, CTHREADS>>>(lw, hw, out);
}